// round 16
// baseline (speedup 1.0000x reference)
#include <cuda_runtime.h>
#include <cuda_bf16.h>
#include <math.h>
#include <stdint.h>
#include <cstdint>

#define NATOMS 30000
#define NPAIRS 1200000
#define NBASIS 7
#define NRAD   5
#define NSPEC  119
#define NFEAT  360
#define NFEATP 368          // layer-1 K padded to multiple of 16
#define AP     30080        // atoms padded (unused cols zero)
#define NU1    512
#define NU2    512
#define NSCB   30           // scan blocks
#define NWTOT  (NSPEC * NSPEC * NRAD * NBASIS)

// ---------------- static scratch (no allocations; BSS zero-initialized) ----------------
__device__ int    g_cnt[NATOMS];
__device__ int    g_off[NATOMS];
__device__ int    g_cur[NATOMS];
__device__ int    g_bsum[32];
__device__ int    g_bflag[32];
__device__ float4 g_R4[NATOMS];
__device__ float  g_Wp[(size_t)NSPEC * NSPEC * NRAD * 8];
__device__ float  g_pd[(size_t)NPAIRS * 8];
// feature-major GM [NFEATP][AP] bf16 hi/lo (pads stay zero)
__device__ __nv_bfloat16 g_GMh[(size_t)NFEATP * AP];
__device__ __nv_bfloat16 g_GMl[(size_t)NFEATP * AP];
__device__ __nv_bfloat16 g_w1h[NFEATP * NU1];
__device__ __nv_bfloat16 g_w1l[NFEATP * NU1];
__device__ __nv_bfloat16 g_w2h[NU1 * NU2];
__device__ __nv_bfloat16 g_w2l[NU1 * NU2];
__device__ __nv_bfloat16 g_H1h[(size_t)NATOMS * NU1];
__device__ __nv_bfloat16 g_H1l[(size_t)NATOMS * NU1];

__device__ __forceinline__ void bsplit(float v, __nv_bfloat16& h, __nv_bfloat16& l) {
    h = __float2bfloat16(v);
    l = __float2bfloat16(v - __bfloat162float(h));
}

// ---------------- fused init: prep + packw + weight conversion + scan flags ----------------
__global__ __launch_bounds__(256) void init_kernel(
    const float* __restrict__ R, const int* __restrict__ Z,
    const float* __restrict__ scale, const float* __restrict__ shift,
    const float* __restrict__ b3, float* __restrict__ out,
    const float* __restrict__ Wr,
    const float* __restrict__ w1, const float* __restrict__ w2)
{
    int i = blockIdx.x * blockDim.x + threadIdx.x;
    if (i < 32) g_bflag[i] = 0;
    if (i < NATOMS) {
        g_cnt[i] = 0;
        g_R4[i] = make_float4(R[3*i+0], R[3*i+1], R[3*i+2], 0.0f);
        int z = Z[i];
        out[i] = scale[z] * b3[0] + shift[z];
    }
    if (i < NWTOT) {
        int b = i % NBASIS;
        int rest = i / NBASIS;
        int k = rest % NRAD;
        int pair = rest / NRAD;
        g_Wp[((size_t)pair * NRAD + k) * 8 + b] = Wr[i];
    }
    if (i < NFEATP * NU1) {
        int k = i / NU1, n = i % NU1;
        float v = (k < NFEAT) ? w1[(size_t)k * NU1 + n] : 0.0f;
        bsplit(v, g_w1h[i], g_w1l[i]);
    }
    if (i < NU1 * NU2) {
        bsplit(w2[i], g_w2h[i], g_w2l[i]);
    }
}

// ---------------- histogram (4 pairs per thread) ----------------
__global__ __launch_bounds__(256) void hist_kernel(const int* __restrict__ idx) {
    int t = blockIdx.x * blockDim.x + threadIdx.x;
    if (t < NPAIRS / 4) {
        int4 v = ((const int4*)idx)[t];
        atomicAdd(&g_cnt[v.x], 1);
        atomicAdd(&g_cnt[v.y], 1);
        atomicAdd(&g_cnt[v.z], 1);
        atomicAdd(&g_cnt[v.w], 1);
    }
}

// ---------------- single-kernel scan (decoupled lookback over 30 resident blocks) ----------------
__global__ __launch_bounds__(1024) void scan_kernel() {
    __shared__ int wsum[32];
    __shared__ int sprefix;
    int tid = threadIdx.x, lane = tid & 31, w = tid >> 5;
    int b = blockIdx.x;
    int i = b * 1024 + tid;
    int v = (i < NATOMS) ? g_cnt[i] : 0;
    int x = v;
#pragma unroll
    for (int o = 1; o < 32; o <<= 1) {
        int y = __shfl_up_sync(0xffffffffu, x, o);
        if (lane >= o) x += y;
    }
    if (lane == 31) wsum[w] = x;
    __syncthreads();
    if (w == 0) {
        int t = wsum[lane];
        int xs = t;
#pragma unroll
        for (int o = 1; o < 32; o <<= 1) {
            int y = __shfl_up_sync(0xffffffffu, xs, o);
            if (lane >= o) xs += y;
        }
        wsum[lane] = xs - t;
    }
    __syncthreads();
    int local_ex = wsum[w] + x - v;          // exclusive within block
    // publish block total
    if (tid == 1023) {
        g_bsum[b] = wsum[31] + x;
        __threadfence();
        atomicExch(&g_bflag[b], 1);
    }
    // thread 0 gathers prefix of preceding blocks
    if (tid == 0) {
        int pre = 0;
        for (int j = 0; j < b; j++) {
            while (atomicAdd(&g_bflag[j], 0) == 0) { }
            pre += g_bsum[j];
        }
        sprefix = pre;
    }
    __syncthreads();
    if (i < NATOMS) {
        int o = local_ex + sprefix;
        g_off[i] = o;
        g_cur[i] = o;
    }
}

// ---------------- per-pair math + scatter (2 pairs/thread for MLP) ----------------
__global__ __launch_bounds__(256) void scatter_kernel(
    const int* __restrict__ Z, const int* __restrict__ idx)
{
    int t = blockIdx.x * blockDim.x + threadIdx.x;
    int p0 = t * 2;
    if (p0 >= NPAIRS) return;

    int i0 = idx[p0],     j0 = idx[NPAIRS + p0];
    int i1 = idx[p0 + 1], j1 = idx[NPAIRS + p0 + 1];
    float4 Ri0 = g_R4[i0], Rj0 = g_R4[j0];
    float4 Ri1 = g_R4[i1], Rj1 = g_R4[j1];
    int zi0 = Z[i0], zj0 = Z[j0];
    int zi1 = Z[i1], zj1 = Z[j1];

    const float4* cf0 = (const float4*)(g_Wp + (size_t)(zi0 * NSPEC + zj0) * NRAD * 8);
    const float4* cf1 = (const float4*)(g_Wp + (size_t)(zi1 * NSPEC + zj1) * NRAD * 8);

    const float PI = 3.14159265358979323846f;
    const float betta = 49.0f / 36.0f;
    const float rn = 0.9601717136386805f;

#pragma unroll
    for (int q = 0; q < 2; q++) {
        float4 Ri = q ? Ri1 : Ri0;
        float4 Rj = q ? Rj1 : Rj0;
        const float4* cf4 = q ? cf1 : cf0;
        int i = q ? i1 : i0;

        float dx = Rj.x - Ri.x;
        float dy = Rj.y - Ri.y;
        float dz = Rj.z - Ri.z;
        float dr = sqrtf(dx*dx + dy*dy + dz*dz + 1e-12f);

        float cut = (dr < 6.0f)
                  ? 0.5f * (__cosf((PI / 6.0f) * dr) + 1.0f) * 0.37796447300922720f
                  : 0.0f;

        float inv = 1.0f / (dr + 1e-5f);
        float ux = dx * inv, uy = dy * inv, uz = dz * inv;

        float basis[NBASIS];
#pragma unroll
        for (int b = 0; b < NBASIS; b++) {
            float d = dr - (0.5f + 0.7857142857142857f * (float)b);
            basis[b] = rn * __expf(-betta * d * d);
        }

        float radial[NRAD];
#pragma unroll
        for (int k = 0; k < NRAD; k++) {
            float4 c0 = cf4[k * 2];
            float4 c1 = cf4[k * 2 + 1];
            float s = c0.x * basis[0];
            s = fmaf(c0.y, basis[1], s);
            s = fmaf(c0.z, basis[2], s);
            s = fmaf(c0.w, basis[3], s);
            s = fmaf(c1.x, basis[4], s);
            s = fmaf(c1.y, basis[5], s);
            s = fmaf(c1.z, basis[6], s);
            radial[k] = s * cut;
        }

        int pos = atomicAdd(&g_cur[i], 1);
        float4 lo = make_float4(radial[0], radial[1], radial[2], radial[3]);
        float4 hi = make_float4(radial[4], ux, uy, uz);
        *(float4*)&g_pd[(size_t)pos * 8 + 0] = lo;
        *(float4*)&g_pd[(size_t)pos * 8 + 4] = hi;
    }
}

// ---------------- fused: moment accumulation (unroll-2) + invariants -> feature-major bf16 ----------------
__global__ __launch_bounds__(128) void moments_kernel()
{
    int a = blockIdx.x * blockDim.x + threadIdx.x;
    if (a >= NATOMS) return;

    int beg = g_off[a];
    int end = beg + g_cnt[a];

    float acc[NRAD][20];
#pragma unroll
    for (int k = 0; k < NRAD; k++)
#pragma unroll
        for (int m = 0; m < 20; m++) acc[k][m] = 0.0f;

    auto body = [&](float4 lo, float4 hi) {
        float rad[NRAD] = {lo.x, lo.y, lo.z, lo.w, hi.x};
        float ux = hi.y, uy = hi.z, uz = hi.w;
        float g[20];
        g[0] = 1.0f;
        g[1] = ux; g[2] = uy; g[3] = uz;
        float xx = ux*ux, yy = uy*uy, zz = uz*uz;
        float xy = ux*uy, xz = ux*uz, yz = uy*uz;
        g[4] = xx; g[5] = yy; g[6] = zz; g[7] = xy; g[8] = xz; g[9] = yz;
        g[10] = xx*ux; g[11] = xx*uy; g[12] = xx*uz;
        g[13] = yy*ux; g[14] = xy*uz; g[15] = zz*ux;
        g[16] = yy*uy; g[17] = yy*uz; g[18] = zz*uy; g[19] = zz*uz;
#pragma unroll
        for (int k = 0; k < NRAD; k++)
#pragma unroll
            for (int m = 0; m < 20; m++)
                acc[k][m] = fmaf(rad[k], g[m], acc[k][m]);
    };

    int p = beg;
    for (; p + 1 < end; p += 2) {
        float4 lo0 = *(const float4*)&g_pd[(size_t)p * 8 + 0];
        float4 hi0 = *(const float4*)&g_pd[(size_t)p * 8 + 4];
        float4 lo1 = *(const float4*)&g_pd[(size_t)(p + 1) * 8 + 0];
        float4 hi1 = *(const float4*)&g_pd[(size_t)(p + 1) * 8 + 4];
        body(lo0, hi0);
        body(lo1, hi1);
    }
    if (p < end) {
        float4 lo = *(const float4*)&g_pd[(size_t)p * 8 + 0];
        float4 hi = *(const float4*)&g_pd[(size_t)p * 8 + 4];
        body(lo, hi);
    }

    // ---- expand symmetric moments and emit 360 features (feature-major, coalesced) ----
    const int T2[9]  = {0,3,4, 3,1,5, 4,5,2};
    const int T3[27] = {0,1,2, 1,3,4, 2,4,5,
                        1,3,4, 3,6,7, 4,7,8,
                        2,4,5, 4,7,8, 5,8,9};

    float m0v[NRAD];
    float m1v[NRAD][3];
    float m2v[NRAD][9];
    float m3v[NRAD][27];
    for (int k = 0; k < NRAD; k++) {
        m0v[k] = acc[k][0];
        for (int d = 0; d < 3; d++) m1v[k][d] = acc[k][1 + d];
        for (int e = 0; e < 9; e++)  m2v[k][e] = acc[k][4 + T2[e]];
        for (int e = 0; e < 27; e++) m3v[k][e] = acc[k][10 + T3[e]];
    }

    int f = 0;
#define EMIT(v) do { __nv_bfloat16 _h, _l; bsplit((v), _h, _l); \
    g_GMh[(size_t)(f) * AP + a] = _h; g_GMl[(size_t)(f) * AP + a] = _l; f++; } while (0)

    for (int k = 0; k < NRAD; k++) EMIT(m0v[k]);

    for (int r = 0; r < NRAD; r++)
        for (int s = r; s < NRAD; s++) {
            float v = m1v[r][0]*m1v[s][0] + m1v[r][1]*m1v[s][1] + m1v[r][2]*m1v[s][2];
            EMIT(v);
        }

    for (int r = 0; r < NRAD; r++)
        for (int s = r; s < NRAD; s++) {
            float v = 0.0f;
            for (int e = 0; e < 9; e++) v = fmaf(m2v[r][e], m2v[s][e], v);
            EMIT(v);
        }

    for (int r = 0; r < NRAD; r++)
        for (int s = r; s < NRAD; s++) {
            float v = 0.0f;
            for (int e = 0; e < 27; e++) v = fmaf(m3v[r][e], m3v[s][e], v);
            EMIT(v);
        }

    for (int r = 0; r < NRAD; r++)
        for (int s = r; s < NRAD; s++)
            for (int t = s; t < NRAD; t++) {
                float v = 0.0f;
                for (int jj = 0; jj < 3; jj++)
                    for (int kk = 0; kk < 3; kk++) {
                        float pjk = 0.0f;
                        for (int ii = 0; ii < 3; ii++)
                            pjk = fmaf(m2v[r][ii*3 + jj], m2v[s][ii*3 + kk], pjk);
                        v = fmaf(pjk, m2v[t][jj*3 + kk], v);
                    }
                EMIT(v);
            }

    for (int r = 0; r < NRAD; r++)
        for (int s = r; s < NRAD; s++) {
            float O[9];
            for (int ii = 0; ii < 3; ii++)
                for (int jj = 0; jj < 3; jj++)
                    O[ii*3 + jj] = m1v[r][ii] * m1v[s][jj];
            for (int t = 0; t < NRAD; t++) {
                float v = 0.0f;
                for (int e = 0; e < 9; e++) v = fmaf(O[e], m2v[t][e], v);
                EMIT(v);
            }
        }

    for (int r = 0; r < NRAD; r++)
        for (int s = r; s < NRAD; s++) {
            float T[9];
            for (int kk = 0; kk < 3; kk++)
                for (int ll = 0; ll < 3; ll++) {
                    float acc2 = 0.0f;
                    for (int ij = 0; ij < 9; ij++)
                        acc2 = fmaf(m3v[r][ij*3 + kk], m3v[s][ij*3 + ll], acc2);
                    T[kk*3 + ll] = acc2;
                }
            for (int t = 0; t < NRAD; t++) {
                float v = 0.0f;
                for (int e = 0; e < 9; e++) v = fmaf(T[e], m2v[t][e], v);
                EMIT(v);
            }
        }

    for (int r = 0; r < NRAD; r++)
        for (int s = 0; s < NRAD; s++) {
            float w[3];
            for (int kk = 0; kk < 3; kk++) {
                float acc2 = 0.0f;
                for (int ij = 0; ij < 9; ij++)
                    acc2 = fmaf(m3v[r][ij*3 + kk], m2v[s][ij], acc2);
                w[kk] = acc2;
            }
            for (int t = 0; t < NRAD; t++) {
                float v = w[0]*m1v[t][0] + w[1]*m1v[t][1] + w[2]*m1v[t][2];
                EMIT(v);
            }
        }
#undef EMIT
}

// ============================================================================
// bf16x3 tensor-core GEMMs (mma.sync), R13 2-stage cp.async schedule.
// LAYER1: GM([K][M] feature-major) -> H1 bf16 hi/lo (swish), trans-ldsm A.
// LAYER2: H1([M][K]) -> fused layer-3 dot -> out.
// ============================================================================
#define AS_STR  24
#define KM_STR  136

__device__ __forceinline__ unsigned smem_u32(const void* p) {
    return (unsigned)__cvta_generic_to_shared(p);
}
__device__ __forceinline__ void cpa16(void* s, const void* g) {
    asm volatile("cp.async.cg.shared.global [%0], [%1], 16;"
                 :: "r"(smem_u32(s)), "l"(g) : "memory");
}
__device__ __forceinline__ void cp_commit() {
    asm volatile("cp.async.commit_group;" ::: "memory");
}
__device__ __forceinline__ void cp_wait0() {
    asm volatile("cp.async.wait_group 0;" ::: "memory");
}
__device__ __forceinline__ void ldsm4(unsigned* r, unsigned addr) {
    asm volatile("ldmatrix.sync.aligned.m8n8.x4.shared.b16 {%0,%1,%2,%3}, [%4];"
        : "=r"(r[0]), "=r"(r[1]), "=r"(r[2]), "=r"(r[3]) : "r"(addr));
}
__device__ __forceinline__ void ldsm4t(unsigned* r, unsigned addr) {
    asm volatile("ldmatrix.sync.aligned.m8n8.x4.trans.shared.b16 {%0,%1,%2,%3}, [%4];"
        : "=r"(r[0]), "=r"(r[1]), "=r"(r[2]), "=r"(r[3]) : "r"(addr));
}
__device__ __forceinline__ void mma_bf16(float* d, const unsigned* a, unsigned b0, unsigned b1) {
    asm volatile("mma.sync.aligned.m16n8k16.row.col.f32.bf16.bf16.f32 "
        "{%0,%1,%2,%3}, {%4,%5,%6,%7}, {%8,%9}, {%0,%1,%2,%3};"
        : "+f"(d[0]), "+f"(d[1]), "+f"(d[2]), "+f"(d[3])
        : "r"(a[0]), "r"(a[1]), "r"(a[2]), "r"(a[3]), "r"(b0), "r"(b1));
}

template<int LAYER>
__global__ __launch_bounds__(256, 2) void mma_gemm_kernel(
    const __nv_bfloat16* __restrict__ Ah, const __nv_bfloat16* __restrict__ Al,
    const __nv_bfloat16* __restrict__ Bh, const __nv_bfloat16* __restrict__ Bl,
    const float* __restrict__ bias,
    int M, int N, int K, int Astride,
    const float* __restrict__ w3, const float* __restrict__ scale,
    const int* __restrict__ Z, float* __restrict__ out)
{
    __shared__ __align__(16) __nv_bfloat16 Ash[2][2][(16 * KM_STR > 128 * AS_STR) ? 16 * KM_STR : 128 * AS_STR];
    __shared__ __align__(16) __nv_bfloat16 Bsh[2][2][16 * KM_STR];

    int tid = threadIdx.x;
    int lane = tid & 31;
    int wid = tid >> 5;
    int wm = wid & 3;
    int wn = wid >> 2;
    int m0 = blockIdx.y * 128;
    int n0 = blockIdx.x * 128;

    int lk = tid >> 4;             // 0..15 (k row) [LAYER1 A, and B]
    int lm8 = (tid & 15) * 8;      // m/n offset
    int lmB = tid >> 1;            // LAYER2 A: m row 0..127
    int lkg = (tid & 1) * 8;       // LAYER2 A: k offset

    float acc[2][8][4];
#pragma unroll
    for (int f = 0; f < 2; f++)
#pragma unroll
        for (int n8 = 0; n8 < 8; n8++)
#pragma unroll
            for (int q = 0; q < 4; q++) acc[f][n8][q] = 0.0f;

    int nT = K / 16;

    auto issue_tile = [&](int kt, int buf) {
        if (LAYER == 1) {
            size_t off = (size_t)(kt + lk) * Astride + m0 + lm8;
            cpa16(&Ash[buf][0][lk * KM_STR + lm8], &Ah[off]);
            cpa16(&Ash[buf][1][lk * KM_STR + lm8], &Al[off]);
        } else {
            int gm = m0 + lmB;
            if (gm >= M) gm = M - 1;
            size_t off = (size_t)gm * K + kt + lkg;
            cpa16(&Ash[buf][0][lmB * AS_STR + lkg], &Ah[off]);
            cpa16(&Ash[buf][1][lmB * AS_STR + lkg], &Al[off]);
        }
        size_t woff = (size_t)(kt + lk) * N + n0 + lm8;
        cpa16(&Bsh[buf][0][lk * KM_STR + lm8], &Bh[woff]);
        cpa16(&Bsh[buf][1][lk * KM_STR + lm8], &Bl[woff]);
    };

    unsigned aoff;
    if (LAYER == 1) {
        int krow = (lane & 7) + ((lane >> 4) << 3);
        int mcol = wm * 32 + (((lane >> 3) & 1) << 3);
        aoff = (krow * KM_STR + mcol) * 2;
    } else {
        aoff = ((wm * 32 + (lane & 15)) * AS_STR + (lane >> 4) * 8) * 2;
    }
    unsigned boff = ((lane & 15) * KM_STR + wn * 64 + (lane >> 4) * 8) * 2;

    issue_tile(0, 0);
    cp_commit();
    cp_wait0();
    __syncthreads();

    for (int t = 0; t < nT; t++) {
        int cur = t & 1;
        bool has = (t + 1 < nT);
        if (has) { issue_tile((t + 1) * 16, cur ^ 1); cp_commit(); }

        unsigned aBaseH = smem_u32(&Ash[cur][0][0]) + aoff;
        unsigned aBaseL = smem_u32(&Ash[cur][1][0]) + aoff;
        unsigned bBaseH = smem_u32(&Bsh[cur][0][0]) + boff;
        unsigned bBaseL = smem_u32(&Bsh[cur][1][0]) + boff;

        unsigned ah[2][4], al[2][4], bh[4][4], bl[4][4];
#pragma unroll
        for (int f = 0; f < 2; f++) {
            if (LAYER == 1) {
                ldsm4t(ah[f], aBaseH + f * 16 * 2);
                ldsm4t(al[f], aBaseL + f * 16 * 2);
            } else {
                ldsm4(ah[f], aBaseH + f * 16 * AS_STR * 2);
                ldsm4(al[f], aBaseL + f * 16 * AS_STR * 2);
            }
        }
#pragma unroll
        for (int nb = 0; nb < 4; nb++) {
            ldsm4t(bh[nb], bBaseH + nb * 32);
            ldsm4t(bl[nb], bBaseL + nb * 32);
        }

#pragma unroll
        for (int f = 0; f < 2; f++)
#pragma unroll
            for (int nb = 0; nb < 4; nb++)
#pragma unroll
                for (int j = 0; j < 2; j++) {
                    float* d = acc[f][nb * 2 + j];
                    unsigned bh0 = bh[nb][2 * j], bh1 = bh[nb][2 * j + 1];
                    unsigned bl0 = bl[nb][2 * j], bl1 = bl[nb][2 * j + 1];
                    mma_bf16(d, ah[f], bh0, bh1);
                    mma_bf16(d, ah[f], bl0, bl1);
                    mma_bf16(d, al[f], bh0, bh1);
                }

        if (has) cp_wait0();
        __syncthreads();
    }

    // ---- epilogue ----
    if (LAYER == 1) {
#pragma unroll
        for (int f = 0; f < 2; f++)
#pragma unroll
            for (int n8 = 0; n8 < 8; n8++) {
                int rm = m0 + wm * 32 + f * 16 + (lane >> 2);
                int cn = n0 + wn * 64 + n8 * 8 + (lane & 3) * 2;
                float b0 = bias[cn], b1 = bias[cn + 1];
#pragma unroll
                for (int half = 0; half < 2; half++) {
                    int r = rm + half * 8;
                    if (r >= M) continue;
                    float v0 = acc[f][n8][half * 2 + 0] + b0;
                    float v1 = acc[f][n8][half * 2 + 1] + b1;
                    v0 = v0 / (1.0f + __expf(-v0));
                    v1 = v1 / (1.0f + __expf(-v1));
                    __nv_bfloat16 h0, l0, h1, l1;
                    bsplit(v0, h0, l0); bsplit(v1, h1, l1);
                    *(__nv_bfloat162*)&g_H1h[(size_t)r * NU1 + cn] = __nv_bfloat162(h0, h1);
                    *(__nv_bfloat162*)&g_H1l[(size_t)r * NU1 + cn] = __nv_bfloat162(l0, l1);
                }
            }
    } else {
        float rs[2][2] = {{0.0f, 0.0f}, {0.0f, 0.0f}};
#pragma unroll
        for (int f = 0; f < 2; f++)
#pragma unroll
            for (int n8 = 0; n8 < 8; n8++) {
                int cn = n0 + wn * 64 + n8 * 8 + (lane & 3) * 2;
                float b0 = bias[cn], b1 = bias[cn + 1];
                float w0 = w3[cn], w1 = w3[cn + 1];
#pragma unroll
                for (int half = 0; half < 2; half++) {
                    float v0 = acc[f][n8][half * 2 + 0] + b0;
                    float v1 = acc[f][n8][half * 2 + 1] + b1;
                    v0 = v0 / (1.0f + __expf(-v0));
                    v1 = v1 / (1.0f + __expf(-v1));
                    rs[f][half] = fmaf(v0, w0, fmaf(v1, w1, rs[f][half]));
                }
            }
#pragma unroll
        for (int f = 0; f < 2; f++)
#pragma unroll
            for (int half = 0; half < 2; half++) {
                float s = rs[f][half];
                s += __shfl_xor_sync(0xffffffffu, s, 1);
                s += __shfl_xor_sync(0xffffffffu, s, 2);
                if ((lane & 3) == 0) {
                    int r = m0 + wm * 32 + f * 16 + (lane >> 2) + half * 8;
                    if (r < M) {
                        atomicAdd(&out[r], scale[Z[r]] * s);
                    }
                }
            }
    }
}

// ---------------- launch ----------------
extern "C" void kernel_launch(void* const* d_in, const int* in_sizes, int n_in,
                              void* d_out, int out_size)
{
    const float* R     = (const float*)d_in[0];
    const int*   Z     = (const int*)  d_in[1];
    const int*   idx   = (const int*)  d_in[2];
    const float* Wr    = (const float*)d_in[3];
    const float* w1    = (const float*)d_in[4];
    const float* b1    = (const float*)d_in[5];
    const float* w2    = (const float*)d_in[6];
    const float* b2    = (const float*)d_in[7];
    const float* w3    = (const float*)d_in[8];
    const float* b3    = (const float*)d_in[9];
    const float* scale = (const float*)d_in[10];
    const float* shift = (const float*)d_in[11];
    float* out = (float*)d_out;

    __nv_bfloat16 *pGMh, *pGMl, *pW1h, *pW1l, *pW2h, *pW2l, *pH1h, *pH1l;
    cudaGetSymbolAddress((void**)&pGMh, g_GMh);
    cudaGetSymbolAddress((void**)&pGMl, g_GMl);
    cudaGetSymbolAddress((void**)&pW1h, g_w1h);
    cudaGetSymbolAddress((void**)&pW1l, g_w1l);
    cudaGetSymbolAddress((void**)&pW2h, g_w2h);
    cudaGetSymbolAddress((void**)&pW2l, g_w2l);
    cudaGetSymbolAddress((void**)&pH1h, g_H1h);
    cudaGetSymbolAddress((void**)&pH1l, g_H1l);

    init_kernel<<<(NWTOT + 255) / 256, 256>>>(R, Z, scale, shift, b3, out, Wr, w1, w2);
    hist_kernel<<<(NPAIRS / 4 + 255) / 256, 256>>>(idx);
    scan_kernel<<<NSCB, 1024>>>();
    scatter_kernel<<<(NPAIRS / 2 + 255) / 256, 256>>>(Z, idx);
    moments_kernel<<<(NATOMS + 127) / 128, 128>>>();

    dim3 g1(NU1 / 128, (NATOMS + 127) / 128);
    mma_gemm_kernel<1><<<g1, 256>>>(pGMh, pGMl, pW1h, pW1l, b1, NATOMS, NU1, NFEATP, AP,
                                    nullptr, nullptr, nullptr, nullptr);

    dim3 g2(NU2 / 128, (NATOMS + 127) / 128);
    mma_gemm_kernel<2><<<g2, 256>>>(pH1h, pH1l, pW2h, pW2l, b2, NATOMS, NU2, NU1, 0,
                                    w3, scale, Z, out);
}

// round 17
// speedup vs baseline: 1.5675x; 1.5675x over previous
#include <cuda_runtime.h>
#include <cuda_bf16.h>
#include <math.h>
#include <stdint.h>
#include <cstdint>

#define NATOMS 30000
#define NPAIRS 1200000
#define NBASIS 7
#define NRAD   5
#define NSPEC  119
#define NFEAT  360
#define NFEATP 368          // layer-1 K padded to multiple of 16
#define AP     30080        // atoms padded (unused cols zero)
#define NU1    512
#define NU2    512
#define NSCB   30           // scan blocks
#define NWTOT  (NSPEC * NSPEC * NRAD * NBASIS)

// ---------------- static scratch (no allocations; BSS zero-initialized) ----------------
__device__ int    g_cnt[NATOMS];
__device__ int    g_off[NATOMS];
__device__ int    g_cur[NATOMS];
__device__ int    g_bsum[32];
__device__ float4 g_R4[NATOMS];
__device__ float  g_Wp[(size_t)NSPEC * NSPEC * NRAD * 8];
__device__ float  g_pd[(size_t)NPAIRS * 8];
// feature-major GM [NFEATP][AP] bf16 hi/lo (pads stay zero)
__device__ __nv_bfloat16 g_GMh[(size_t)NFEATP * AP];
__device__ __nv_bfloat16 g_GMl[(size_t)NFEATP * AP];
__device__ __nv_bfloat16 g_w1h[NFEATP * NU1];
__device__ __nv_bfloat16 g_w1l[NFEATP * NU1];
__device__ __nv_bfloat16 g_w2h[NU1 * NU2];
__device__ __nv_bfloat16 g_w2l[NU1 * NU2];
__device__ __nv_bfloat16 g_H1h[(size_t)NATOMS * NU1];
__device__ __nv_bfloat16 g_H1l[(size_t)NATOMS * NU1];

__device__ __forceinline__ void bsplit(float v, __nv_bfloat16& h, __nv_bfloat16& l) {
    h = __float2bfloat16(v);
    l = __float2bfloat16(v - __bfloat162float(h));
}

// ---------------- fused init: prep + packw + weight conversion ----------------
__global__ __launch_bounds__(256) void init_kernel(
    const float* __restrict__ R, const int* __restrict__ Z,
    const float* __restrict__ scale, const float* __restrict__ shift,
    const float* __restrict__ b3, float* __restrict__ out,
    const float* __restrict__ Wr,
    const float* __restrict__ w1, const float* __restrict__ w2)
{
    int i = blockIdx.x * blockDim.x + threadIdx.x;
    if (i < NATOMS) {
        g_cnt[i] = 0;
        g_R4[i] = make_float4(R[3*i+0], R[3*i+1], R[3*i+2], 0.0f);
        int z = Z[i];
        out[i] = scale[z] * b3[0] + shift[z];
    }
    if (i < NWTOT) {
        int b = i % NBASIS;
        int rest = i / NBASIS;
        int k = rest % NRAD;
        int pair = rest / NRAD;
        g_Wp[((size_t)pair * NRAD + k) * 8 + b] = Wr[i];
    }
    if (i < NFEATP * NU1) {
        int k = i / NU1, n = i % NU1;
        float v = (k < NFEAT) ? w1[(size_t)k * NU1 + n] : 0.0f;
        bsplit(v, g_w1h[i], g_w1l[i]);
    }
    if (i < NU1 * NU2) {
        bsplit(w2[i], g_w2h[i], g_w2l[i]);
    }
}

// ---------------- histogram (4 pairs per thread) ----------------
__global__ __launch_bounds__(256) void hist_kernel(const int* __restrict__ idx) {
    int t = blockIdx.x * blockDim.x + threadIdx.x;
    if (t < NPAIRS / 4) {
        int4 v = ((const int4*)idx)[t];
        atomicAdd(&g_cnt[v.x], 1);
        atomicAdd(&g_cnt[v.y], 1);
        atomicAdd(&g_cnt[v.z], 1);
        atomicAdd(&g_cnt[v.w], 1);
    }
}

// ---------------- 3-phase scan ----------------
__global__ __launch_bounds__(1024) void scan1_kernel() {
    __shared__ int wsum[32];
    int tid = threadIdx.x, lane = tid & 31, w = tid >> 5;
    int i = blockIdx.x * 1024 + tid;
    int v = (i < NATOMS) ? g_cnt[i] : 0;
    int x = v;
#pragma unroll
    for (int o = 1; o < 32; o <<= 1) {
        int y = __shfl_up_sync(0xffffffffu, x, o);
        if (lane >= o) x += y;
    }
    if (lane == 31) wsum[w] = x;
    __syncthreads();
    if (w == 0) {
        int t = wsum[lane];
        int xs = t;
#pragma unroll
        for (int o = 1; o < 32; o <<= 1) {
            int y = __shfl_up_sync(0xffffffffu, xs, o);
            if (lane >= o) xs += y;
        }
        wsum[lane] = xs - t;
    }
    __syncthreads();
    if (i < NATOMS) g_off[i] = wsum[w] + x - v;
    if (tid == 1023) g_bsum[blockIdx.x] = wsum[31] + x;
}
__global__ void scan2_kernel() {
    int lane = threadIdx.x;
    int v = (lane < NSCB) ? g_bsum[lane] : 0;
    int x = v;
#pragma unroll
    for (int o = 1; o < 32; o <<= 1) {
        int y = __shfl_up_sync(0xffffffffu, x, o);
        if (lane >= o) x += y;
    }
    if (lane < NSCB) g_bsum[lane] = x - v;
}
__global__ __launch_bounds__(1024) void scan3_kernel() {
    int i = blockIdx.x * 1024 + threadIdx.x;
    if (i < NATOMS) {
        int o = g_off[i] + g_bsum[blockIdx.x];
        g_off[i] = o;
        g_cur[i] = o;
    }
}

// ---------------- per-pair math + scatter (2 pairs/thread for MLP) ----------------
__global__ __launch_bounds__(256) void scatter_kernel(
    const int* __restrict__ Z, const int* __restrict__ idx)
{
    int t = blockIdx.x * blockDim.x + threadIdx.x;
    int p0 = t * 2;
    if (p0 >= NPAIRS) return;

    int i0 = idx[p0],     j0 = idx[NPAIRS + p0];
    int i1 = idx[p0 + 1], j1 = idx[NPAIRS + p0 + 1];
    float4 Ri0 = g_R4[i0], Rj0 = g_R4[j0];
    float4 Ri1 = g_R4[i1], Rj1 = g_R4[j1];
    int zi0 = Z[i0], zj0 = Z[j0];
    int zi1 = Z[i1], zj1 = Z[j1];

    const float4* cf0 = (const float4*)(g_Wp + (size_t)(zi0 * NSPEC + zj0) * NRAD * 8);
    const float4* cf1 = (const float4*)(g_Wp + (size_t)(zi1 * NSPEC + zj1) * NRAD * 8);

    const float PI = 3.14159265358979323846f;
    const float betta = 49.0f / 36.0f;
    const float rn = 0.9601717136386805f;

#pragma unroll
    for (int q = 0; q < 2; q++) {
        float4 Ri = q ? Ri1 : Ri0;
        float4 Rj = q ? Rj1 : Rj0;
        const float4* cf4 = q ? cf1 : cf0;
        int i = q ? i1 : i0;

        float dx = Rj.x - Ri.x;
        float dy = Rj.y - Ri.y;
        float dz = Rj.z - Ri.z;
        float dr = sqrtf(dx*dx + dy*dy + dz*dz + 1e-12f);

        float cut = (dr < 6.0f)
                  ? 0.5f * (__cosf((PI / 6.0f) * dr) + 1.0f) * 0.37796447300922720f
                  : 0.0f;

        float inv = 1.0f / (dr + 1e-5f);
        float ux = dx * inv, uy = dy * inv, uz = dz * inv;

        float basis[NBASIS];
#pragma unroll
        for (int b = 0; b < NBASIS; b++) {
            float d = dr - (0.5f + 0.7857142857142857f * (float)b);
            basis[b] = rn * __expf(-betta * d * d);
        }

        float radial[NRAD];
#pragma unroll
        for (int k = 0; k < NRAD; k++) {
            float4 c0 = cf4[k * 2];
            float4 c1 = cf4[k * 2 + 1];
            float s = c0.x * basis[0];
            s = fmaf(c0.y, basis[1], s);
            s = fmaf(c0.z, basis[2], s);
            s = fmaf(c0.w, basis[3], s);
            s = fmaf(c1.x, basis[4], s);
            s = fmaf(c1.y, basis[5], s);
            s = fmaf(c1.z, basis[6], s);
            radial[k] = s * cut;
        }

        int pos = atomicAdd(&g_cur[i], 1);
        float4 lo = make_float4(radial[0], radial[1], radial[2], radial[3]);
        float4 hi = make_float4(radial[4], ux, uy, uz);
        *(float4*)&g_pd[(size_t)pos * 8 + 0] = lo;
        *(float4*)&g_pd[(size_t)pos * 8 + 4] = hi;
    }
}

// ---------------- fused: moment accumulation (unroll-2) + invariants -> feature-major bf16 ----------------
__global__ __launch_bounds__(128) void moments_kernel()
{
    int a = blockIdx.x * blockDim.x + threadIdx.x;
    if (a >= NATOMS) return;

    int beg = g_off[a];
    int end = beg + g_cnt[a];

    float acc[NRAD][20];
#pragma unroll
    for (int k = 0; k < NRAD; k++)
#pragma unroll
        for (int m = 0; m < 20; m++) acc[k][m] = 0.0f;

    auto body = [&](float4 lo, float4 hi) {
        float rad[NRAD] = {lo.x, lo.y, lo.z, lo.w, hi.x};
        float ux = hi.y, uy = hi.z, uz = hi.w;
        float g[20];
        g[0] = 1.0f;
        g[1] = ux; g[2] = uy; g[3] = uz;
        float xx = ux*ux, yy = uy*uy, zz = uz*uz;
        float xy = ux*uy, xz = ux*uz, yz = uy*uz;
        g[4] = xx; g[5] = yy; g[6] = zz; g[7] = xy; g[8] = xz; g[9] = yz;
        g[10] = xx*ux; g[11] = xx*uy; g[12] = xx*uz;
        g[13] = yy*ux; g[14] = xy*uz; g[15] = zz*ux;
        g[16] = yy*uy; g[17] = yy*uz; g[18] = zz*uy; g[19] = zz*uz;
#pragma unroll
        for (int k = 0; k < NRAD; k++)
#pragma unroll
            for (int m = 0; m < 20; m++)
                acc[k][m] = fmaf(rad[k], g[m], acc[k][m]);
    };

    int p = beg;
    for (; p + 1 < end; p += 2) {
        float4 lo0 = *(const float4*)&g_pd[(size_t)p * 8 + 0];
        float4 hi0 = *(const float4*)&g_pd[(size_t)p * 8 + 4];
        float4 lo1 = *(const float4*)&g_pd[(size_t)(p + 1) * 8 + 0];
        float4 hi1 = *(const float4*)&g_pd[(size_t)(p + 1) * 8 + 4];
        body(lo0, hi0);
        body(lo1, hi1);
    }
    if (p < end) {
        float4 lo = *(const float4*)&g_pd[(size_t)p * 8 + 0];
        float4 hi = *(const float4*)&g_pd[(size_t)p * 8 + 4];
        body(lo, hi);
    }

    // ---- expand symmetric moments and emit 360 features (feature-major, coalesced) ----
    const int T2[9]  = {0,3,4, 3,1,5, 4,5,2};
    const int T3[27] = {0,1,2, 1,3,4, 2,4,5,
                        1,3,4, 3,6,7, 4,7,8,
                        2,4,5, 4,7,8, 5,8,9};

    float m0v[NRAD];
    float m1v[NRAD][3];
    float m2v[NRAD][9];
    float m3v[NRAD][27];
    for (int k = 0; k < NRAD; k++) {
        m0v[k] = acc[k][0];
        for (int d = 0; d < 3; d++) m1v[k][d] = acc[k][1 + d];
        for (int e = 0; e < 9; e++)  m2v[k][e] = acc[k][4 + T2[e]];
        for (int e = 0; e < 27; e++) m3v[k][e] = acc[k][10 + T3[e]];
    }

    int f = 0;
#define EMIT(v) do { __nv_bfloat16 _h, _l; bsplit((v), _h, _l); \
    g_GMh[(size_t)(f) * AP + a] = _h; g_GMl[(size_t)(f) * AP + a] = _l; f++; } while (0)

    for (int k = 0; k < NRAD; k++) EMIT(m0v[k]);

    for (int r = 0; r < NRAD; r++)
        for (int s = r; s < NRAD; s++) {
            float v = m1v[r][0]*m1v[s][0] + m1v[r][1]*m1v[s][1] + m1v[r][2]*m1v[s][2];
            EMIT(v);
        }

    for (int r = 0; r < NRAD; r++)
        for (int s = r; s < NRAD; s++) {
            float v = 0.0f;
            for (int e = 0; e < 9; e++) v = fmaf(m2v[r][e], m2v[s][e], v);
            EMIT(v);
        }

    for (int r = 0; r < NRAD; r++)
        for (int s = r; s < NRAD; s++) {
            float v = 0.0f;
            for (int e = 0; e < 27; e++) v = fmaf(m3v[r][e], m3v[s][e], v);
            EMIT(v);
        }

    for (int r = 0; r < NRAD; r++)
        for (int s = r; s < NRAD; s++)
            for (int t = s; t < NRAD; t++) {
                float v = 0.0f;
                for (int jj = 0; jj < 3; jj++)
                    for (int kk = 0; kk < 3; kk++) {
                        float pjk = 0.0f;
                        for (int ii = 0; ii < 3; ii++)
                            pjk = fmaf(m2v[r][ii*3 + jj], m2v[s][ii*3 + kk], pjk);
                        v = fmaf(pjk, m2v[t][jj*3 + kk], v);
                    }
                EMIT(v);
            }

    for (int r = 0; r < NRAD; r++)
        for (int s = r; s < NRAD; s++) {
            float O[9];
            for (int ii = 0; ii < 3; ii++)
                for (int jj = 0; jj < 3; jj++)
                    O[ii*3 + jj] = m1v[r][ii] * m1v[s][jj];
            for (int t = 0; t < NRAD; t++) {
                float v = 0.0f;
                for (int e = 0; e < 9; e++) v = fmaf(O[e], m2v[t][e], v);
                EMIT(v);
            }
        }

    for (int r = 0; r < NRAD; r++)
        for (int s = r; s < NRAD; s++) {
            float T[9];
            for (int kk = 0; kk < 3; kk++)
                for (int ll = 0; ll < 3; ll++) {
                    float acc2 = 0.0f;
                    for (int ij = 0; ij < 9; ij++)
                        acc2 = fmaf(m3v[r][ij*3 + kk], m3v[s][ij*3 + ll], acc2);
                    T[kk*3 + ll] = acc2;
                }
            for (int t = 0; t < NRAD; t++) {
                float v = 0.0f;
                for (int e = 0; e < 9; e++) v = fmaf(T[e], m2v[t][e], v);
                EMIT(v);
            }
        }

    for (int r = 0; r < NRAD; r++)
        for (int s = 0; s < NRAD; s++) {
            float w[3];
            for (int kk = 0; kk < 3; kk++) {
                float acc2 = 0.0f;
                for (int ij = 0; ij < 9; ij++)
                    acc2 = fmaf(m3v[r][ij*3 + kk], m2v[s][ij], acc2);
                w[kk] = acc2;
            }
            for (int t = 0; t < NRAD; t++) {
                float v = w[0]*m1v[t][0] + w[1]*m1v[t][1] + w[2]*m1v[t][2];
                EMIT(v);
            }
        }
#undef EMIT
}

// ============================================================================
// bf16x3 tensor-core GEMMs (mma.sync), 2-stage cp.async schedule (R13).
// LAYER1: GM([K][M] feature-major) -> H1 bf16 hi/lo (swish), trans-ldsm A.
// LAYER2: H1([M][K]) -> fused layer-3 dot -> out.
// ============================================================================
#define AS_STR  24
#define KM_STR  136

__device__ __forceinline__ unsigned smem_u32(const void* p) {
    return (unsigned)__cvta_generic_to_shared(p);
}
__device__ __forceinline__ void cpa16(void* s, const void* g) {
    asm volatile("cp.async.cg.shared.global [%0], [%1], 16;"
                 :: "r"(smem_u32(s)), "l"(g) : "memory");
}
__device__ __forceinline__ void cp_commit() {
    asm volatile("cp.async.commit_group;" ::: "memory");
}
__device__ __forceinline__ void cp_wait0() {
    asm volatile("cp.async.wait_group 0;" ::: "memory");
}
__device__ __forceinline__ void ldsm4(unsigned* r, unsigned addr) {
    asm volatile("ldmatrix.sync.aligned.m8n8.x4.shared.b16 {%0,%1,%2,%3}, [%4];"
        : "=r"(r[0]), "=r"(r[1]), "=r"(r[2]), "=r"(r[3]) : "r"(addr));
}
__device__ __forceinline__ void ldsm4t(unsigned* r, unsigned addr) {
    asm volatile("ldmatrix.sync.aligned.m8n8.x4.trans.shared.b16 {%0,%1,%2,%3}, [%4];"
        : "=r"(r[0]), "=r"(r[1]), "=r"(r[2]), "=r"(r[3]) : "r"(addr));
}
__device__ __forceinline__ void mma_bf16(float* d, const unsigned* a, unsigned b0, unsigned b1) {
    asm volatile("mma.sync.aligned.m16n8k16.row.col.f32.bf16.bf16.f32 "
        "{%0,%1,%2,%3}, {%4,%5,%6,%7}, {%8,%9}, {%0,%1,%2,%3};"
        : "+f"(d[0]), "+f"(d[1]), "+f"(d[2]), "+f"(d[3])
        : "r"(a[0]), "r"(a[1]), "r"(a[2]), "r"(a[3]), "r"(b0), "r"(b1));
}

template<int LAYER>
__global__ __launch_bounds__(256, 2) void mma_gemm_kernel(
    const __nv_bfloat16* __restrict__ Ah, const __nv_bfloat16* __restrict__ Al,
    const __nv_bfloat16* __restrict__ Bh, const __nv_bfloat16* __restrict__ Bl,
    const float* __restrict__ bias,
    int M, int N, int K, int Astride,
    const float* __restrict__ w3, const float* __restrict__ scale,
    const int* __restrict__ Z, float* __restrict__ out)
{
    __shared__ __align__(16) __nv_bfloat16 Ash[2][2][(16 * KM_STR > 128 * AS_STR) ? 16 * KM_STR : 128 * AS_STR];
    __shared__ __align__(16) __nv_bfloat16 Bsh[2][2][16 * KM_STR];

    int tid = threadIdx.x;
    int lane = tid & 31;
    int wid = tid >> 5;
    int wm = wid & 3;
    int wn = wid >> 2;
    int m0 = blockIdx.y * 128;
    int n0 = blockIdx.x * 128;

    int lk = tid >> 4;             // 0..15 (k row) [LAYER1 A, and B]
    int lm8 = (tid & 15) * 8;      // m/n offset
    int lmB = tid >> 1;            // LAYER2 A: m row 0..127
    int lkg = (tid & 1) * 8;       // LAYER2 A: k offset

    float acc[2][8][4];
#pragma unroll
    for (int f = 0; f < 2; f++)
#pragma unroll
        for (int n8 = 0; n8 < 8; n8++)
#pragma unroll
            for (int q = 0; q < 4; q++) acc[f][n8][q] = 0.0f;

    int nT = K / 16;

    auto issue_tile = [&](int kt, int buf) {
        if (LAYER == 1) {
            size_t off = (size_t)(kt + lk) * Astride + m0 + lm8;
            cpa16(&Ash[buf][0][lk * KM_STR + lm8], &Ah[off]);
            cpa16(&Ash[buf][1][lk * KM_STR + lm8], &Al[off]);
        } else {
            int gm = m0 + lmB;
            if (gm >= M) gm = M - 1;
            size_t off = (size_t)gm * K + kt + lkg;
            cpa16(&Ash[buf][0][lmB * AS_STR + lkg], &Ah[off]);
            cpa16(&Ash[buf][1][lmB * AS_STR + lkg], &Al[off]);
        }
        size_t woff = (size_t)(kt + lk) * N + n0 + lm8;
        cpa16(&Bsh[buf][0][lk * KM_STR + lm8], &Bh[woff]);
        cpa16(&Bsh[buf][1][lk * KM_STR + lm8], &Bl[woff]);
    };

    unsigned aoff;
    if (LAYER == 1) {
        int krow = (lane & 7) + ((lane >> 4) << 3);
        int mcol = wm * 32 + (((lane >> 3) & 1) << 3);
        aoff = (krow * KM_STR + mcol) * 2;
    } else {
        aoff = ((wm * 32 + (lane & 15)) * AS_STR + (lane >> 4) * 8) * 2;
    }
    unsigned boff = ((lane & 15) * KM_STR + wn * 64 + (lane >> 4) * 8) * 2;

    issue_tile(0, 0);
    cp_commit();
    cp_wait0();
    __syncthreads();

    for (int t = 0; t < nT; t++) {
        int cur = t & 1;
        bool has = (t + 1 < nT);
        if (has) { issue_tile((t + 1) * 16, cur ^ 1); cp_commit(); }

        unsigned aBaseH = smem_u32(&Ash[cur][0][0]) + aoff;
        unsigned aBaseL = smem_u32(&Ash[cur][1][0]) + aoff;
        unsigned bBaseH = smem_u32(&Bsh[cur][0][0]) + boff;
        unsigned bBaseL = smem_u32(&Bsh[cur][1][0]) + boff;

        unsigned ah[2][4], al[2][4], bh[4][4], bl[4][4];
#pragma unroll
        for (int f = 0; f < 2; f++) {
            if (LAYER == 1) {
                ldsm4t(ah[f], aBaseH + f * 16 * 2);
                ldsm4t(al[f], aBaseL + f * 16 * 2);
            } else {
                ldsm4(ah[f], aBaseH + f * 16 * AS_STR * 2);
                ldsm4(al[f], aBaseL + f * 16 * AS_STR * 2);
            }
        }
#pragma unroll
        for (int nb = 0; nb < 4; nb++) {
            ldsm4t(bh[nb], bBaseH + nb * 32);
            ldsm4t(bl[nb], bBaseL + nb * 32);
        }

#pragma unroll
        for (int f = 0; f < 2; f++)
#pragma unroll
            for (int nb = 0; nb < 4; nb++)
#pragma unroll
                for (int j = 0; j < 2; j++) {
                    float* d = acc[f][nb * 2 + j];
                    unsigned bh0 = bh[nb][2 * j], bh1 = bh[nb][2 * j + 1];
                    unsigned bl0 = bl[nb][2 * j], bl1 = bl[nb][2 * j + 1];
                    mma_bf16(d, ah[f], bh0, bh1);
                    mma_bf16(d, ah[f], bl0, bl1);
                    mma_bf16(d, al[f], bh0, bh1);
                }

        if (has) cp_wait0();
        __syncthreads();
    }

    // ---- epilogue ----
    if (LAYER == 1) {
#pragma unroll
        for (int f = 0; f < 2; f++)
#pragma unroll
            for (int n8 = 0; n8 < 8; n8++) {
                int rm = m0 + wm * 32 + f * 16 + (lane >> 2);
                int cn = n0 + wn * 64 + n8 * 8 + (lane & 3) * 2;
                float b0 = bias[cn], b1 = bias[cn + 1];
#pragma unroll
                for (int half = 0; half < 2; half++) {
                    int r = rm + half * 8;
                    if (r >= M) continue;
                    float v0 = acc[f][n8][half * 2 + 0] + b0;
                    float v1 = acc[f][n8][half * 2 + 1] + b1;
                    v0 = v0 / (1.0f + __expf(-v0));
                    v1 = v1 / (1.0f + __expf(-v1));
                    __nv_bfloat16 h0, l0, h1, l1;
                    bsplit(v0, h0, l0); bsplit(v1, h1, l1);
                    *(__nv_bfloat162*)&g_H1h[(size_t)r * NU1 + cn] = __nv_bfloat162(h0, h1);
                    *(__nv_bfloat162*)&g_H1l[(size_t)r * NU1 + cn] = __nv_bfloat162(l0, l1);
                }
            }
    } else {
        float rs[2][2] = {{0.0f, 0.0f}, {0.0f, 0.0f}};
#pragma unroll
        for (int f = 0; f < 2; f++)
#pragma unroll
            for (int n8 = 0; n8 < 8; n8++) {
                int cn = n0 + wn * 64 + n8 * 8 + (lane & 3) * 2;
                float b0 = bias[cn], b1 = bias[cn + 1];
                float w0 = w3[cn], w1 = w3[cn + 1];
#pragma unroll
                for (int half = 0; half < 2; half++) {
                    float v0 = acc[f][n8][half * 2 + 0] + b0;
                    float v1 = acc[f][n8][half * 2 + 1] + b1;
                    v0 = v0 / (1.0f + __expf(-v0));
                    v1 = v1 / (1.0f + __expf(-v1));
                    rs[f][half] = fmaf(v0, w0, fmaf(v1, w1, rs[f][half]));
                }
            }
#pragma unroll
        for (int f = 0; f < 2; f++)
#pragma unroll
            for (int half = 0; half < 2; half++) {
                float s = rs[f][half];
                s += __shfl_xor_sync(0xffffffffu, s, 1);
                s += __shfl_xor_sync(0xffffffffu, s, 2);
                if ((lane & 3) == 0) {
                    int r = m0 + wm * 32 + f * 16 + (lane >> 2) + half * 8;
                    if (r < M) {
                        atomicAdd(&out[r], scale[Z[r]] * s);
                    }
                }
            }
    }
}

// ---------------- launch ----------------
extern "C" void kernel_launch(void* const* d_in, const int* in_sizes, int n_in,
                              void* d_out, int out_size)
{
    const float* R     = (const float*)d_in[0];
    const int*   Z     = (const int*)  d_in[1];
    const int*   idx   = (const int*)  d_in[2];
    const float* Wr    = (const float*)d_in[3];
    const float* w1    = (const float*)d_in[4];
    const float* b1    = (const float*)d_in[5];
    const float* w2    = (const float*)d_in[6];
    const float* b2    = (const float*)d_in[7];
    const float* w3    = (const float*)d_in[8];
    const float* b3    = (const float*)d_in[9];
    const float* scale = (const float*)d_in[10];
    const float* shift = (const float*)d_in[11];
    float* out = (float*)d_out;

    __nv_bfloat16 *pGMh, *pGMl, *pW1h, *pW1l, *pW2h, *pW2l, *pH1h, *pH1l;
    cudaGetSymbolAddress((void**)&pGMh, g_GMh);
    cudaGetSymbolAddress((void**)&pGMl, g_GMl);
    cudaGetSymbolAddress((void**)&pW1h, g_w1h);
    cudaGetSymbolAddress((void**)&pW1l, g_w1l);
    cudaGetSymbolAddress((void**)&pW2h, g_w2h);
    cudaGetSymbolAddress((void**)&pW2l, g_w2l);
    cudaGetSymbolAddress((void**)&pH1h, g_H1h);
    cudaGetSymbolAddress((void**)&pH1l, g_H1l);

    init_kernel<<<(NWTOT + 255) / 256, 256>>>(R, Z, scale, shift, b3, out, Wr, w1, w2);
    hist_kernel<<<(NPAIRS / 4 + 255) / 256, 256>>>(idx);
    scan1_kernel<<<NSCB, 1024>>>();
    scan2_kernel<<<1, 32>>>();
    scan3_kernel<<<NSCB, 1024>>>();
    scatter_kernel<<<(NPAIRS / 2 + 255) / 256, 256>>>(Z, idx);
    moments_kernel<<<(NATOMS + 127) / 128, 128>>>();

    dim3 g1(NU1 / 128, (NATOMS + 127) / 128);
    mma_gemm_kernel<1><<<g1, 256>>>(pGMh, pGMl, pW1h, pW1l, b1, NATOMS, NU1, NFEATP, AP,
                                    nullptr, nullptr, nullptr, nullptr);

    dim3 g2(NU2 / 128, (NATOMS + 127) / 128);
    mma_gemm_kernel<2><<<g2, 256>>>(pH1h, pH1l, pW2h, pW2l, b2, NATOMS, NU2, NU1, 0,
                                    w3, scale, Z, out);
}